// round 7
// baseline (speedup 1.0000x reference)
#include <cuda_runtime.h>

#define NN   80000
#define EE   1280000
#define ET   (EE + NN)
#define HH   64
#define FIND 128
#define OUTD 10
#define NCSR 148            // persistent CSR blocks (1 per SM)

// ---------------- scratch ----------------
__device__ float g_xl[(size_t)NN * HH];
__device__ float g_xr[(size_t)NN * HH];
__device__ float g_h1[(size_t)NN * HH];
__device__ float g_h2[(size_t)NN * HH];
__device__ int   g_deg[NN];
__device__ int   g_off[NN + 1];
__device__ int   g_cur[NN];
__device__ int   g_src[ET];
__device__ int   g_bsum[NCSR];
__device__ int   g_bpre[NCSR];
__device__ unsigned g_bar;

// ---------------- tf32 helpers ----------------
__device__ __forceinline__ unsigned f2tf(float v) {
    unsigned u;
    asm("cvt.rna.tf32.f32 %0, %1;" : "=r"(u) : "f"(v));
    return u;
}

// ---------------- GEMM block body (callable from fused + standalone kernels) ----
struct GemmSmem {
    unsigned Af[8 * 4 * 32 * 4];    // 16KB
    unsigned Blf[8 * 4 * 32 * 2];   //  8KB
    unsigned Brf[8 * 4 * 32 * 2];   //  8KB
};

__device__ __forceinline__ void gemm_block(
    GemmSmem& sm, int n0,
    const float* __restrict__ A, int fin,
    const float* __restrict__ Wl, const float* __restrict__ bl,
    const float* __restrict__ Wr, const float* __restrict__ br)
{
    const int t    = threadIdx.x;
    const int lane = t & 31;
    const int w    = t >> 5;

    float accl[8][4], accr[8][4];
    #pragma unroll
    for (int n = 0; n < 8; n++)
        #pragma unroll
        for (int j = 0; j < 4; j++) { accl[n][j] = 0.f; accr[n][j] = 0.f; }

    const int arow0 = t >> 3;
    const int acol4 = t & 7;
    const int wh    = t & 63;
    const int wq    = t >> 6;

    for (int kc = 0; kc < fin; kc += 32) {
        #pragma unroll
        for (int r = 0; r < 4; r++) {
            int row = arow0 + r * 32;
            const float4 v = *(const float4*)(A + (size_t)(n0 + row) * fin + kc + acol4 * 4);
            float vv[4] = {v.x, v.y, v.z, v.w};
            int wi = row >> 4, rl = row & 15;
            #pragma unroll
            for (int cc = 0; cc < 4; cc++) {
                int c  = acol4 * 4 + cc;
                int s  = c >> 3, c4 = c & 7;
                int j  = ((c4 >= 4) ? 2 : 0) + ((rl >= 8) ? 1 : 0);
                int ln = (rl & 7) * 4 + (c4 & 3);
                sm.Af[(((wi * 4 + s) * 32) + ln) * 4 + j] = f2tf(vv[cc]);
            }
        }
        #pragma unroll
        for (int part = 0; part < 2; part++) {
            int kb = wq * 8 + part * 4;
            const float4 v = *(const float4*)(Wl + (size_t)wh * fin + kc + kb);
            const float4 u = *(const float4*)(Wr + (size_t)wh * fin + kc + kb);
            float vl[4] = {v.x, v.y, v.z, v.w};
            float vr[4] = {u.x, u.y, u.z, u.w};
            int nt = wh >> 3;
            #pragma unroll
            for (int cc = 0; cc < 4; cc++) {
                int k  = kb + cc;
                int s  = k >> 3;
                int j  = ((k & 7) >= 4) ? 1 : 0;
                int ln = (wh & 7) * 4 + (k & 3);
                int idx = (((nt * 4 + s) * 32) + ln) * 2 + j;
                sm.Blf[idx] = f2tf(vl[cc]);
                sm.Brf[idx] = f2tf(vr[cc]);
            }
        }
        __syncthreads();

        #pragma unroll
        for (int s = 0; s < 4; s++) {
            uint4 a = *(const uint4*)(sm.Af + (((w * 4 + s) * 32) + lane) * 4);
            #pragma unroll
            for (int n = 0; n < 8; n++) {
                uint2 b = *(const uint2*)(sm.Blf + (((n * 4 + s) * 32) + lane) * 2);
                asm volatile(
                    "mma.sync.aligned.m16n8k8.row.col.f32.tf32.tf32.f32 "
                    "{%0,%1,%2,%3}, {%4,%5,%6,%7}, {%8,%9}, {%0,%1,%2,%3};"
                    : "+f"(accl[n][0]), "+f"(accl[n][1]), "+f"(accl[n][2]), "+f"(accl[n][3])
                    : "r"(a.x), "r"(a.y), "r"(a.z), "r"(a.w), "r"(b.x), "r"(b.y));
                uint2 c = *(const uint2*)(sm.Brf + (((n * 4 + s) * 32) + lane) * 2);
                asm volatile(
                    "mma.sync.aligned.m16n8k8.row.col.f32.tf32.tf32.f32 "
                    "{%0,%1,%2,%3}, {%4,%5,%6,%7}, {%8,%9}, {%0,%1,%2,%3};"
                    : "+f"(accr[n][0]), "+f"(accr[n][1]), "+f"(accr[n][2]), "+f"(accr[n][3])
                    : "r"(a.x), "r"(a.y), "r"(a.z), "r"(a.w), "r"(c.x), "r"(c.y));
            }
        }
        __syncthreads();
    }

    int r0 = n0 + w * 16 + (lane >> 2);
    int cq = (lane & 3) * 2;
    #pragma unroll
    for (int n = 0; n < 8; n++) {
        int col = n * 8 + cq;
        float2 bl2 = *(const float2*)(bl + col);
        float2 br2 = *(const float2*)(br + col);
        float2 o;
        o.x = accl[n][0] + bl2.x; o.y = accl[n][1] + bl2.y;
        *(float2*)(g_xl + (size_t)r0 * HH + col) = o;
        o.x = accl[n][2] + bl2.x; o.y = accl[n][3] + bl2.y;
        *(float2*)(g_xl + (size_t)(r0 + 8) * HH + col) = o;
        o.x = accr[n][0] + br2.x; o.y = accr[n][1] + br2.y;
        *(float2*)(g_xr + (size_t)r0 * HH + col) = o;
        o.x = accr[n][2] + br2.x; o.y = accr[n][3] + br2.y;
        *(float2*)(g_xr + (size_t)(r0 + 8) * HH + col) = o;
    }
}

// ---------------- CSR persistent sub-grid helpers ----------------
__device__ __forceinline__ void grid_bar(int phase) {
    __syncthreads();
    if (threadIdx.x == 0) {
        __threadfence();
        atomicAdd(&g_bar, 1u);
        unsigned target = (unsigned)(NCSR * phase);
        while (atomicAdd(&g_bar, 0u) < target) __nanosleep(64);
        __threadfence();
    }
    __syncthreads();
}

// inclusive block scan over 256 threads; ws = 9 ints of smem
__device__ __forceinline__ int iscan256(int v, int* ws) {
    int lane = threadIdx.x & 31, wid = threadIdx.x >> 5;
    int x = v;
    #pragma unroll
    for (int d = 1; d < 32; d <<= 1) {
        int y = __shfl_up_sync(0xffffffffu, x, d);
        if (lane >= d) x += y;
    }
    if (lane == 31) ws[wid] = x;
    __syncthreads();
    if (threadIdx.x == 0) {
        int run = 0;
        #pragma unroll
        for (int j = 0; j < 8; j++) { int t2 = ws[j]; ws[j] = run; run += t2; }
        ws[8] = run;               // block total
    }
    __syncthreads();
    return x + ws[wid];
}

__device__ void csr_block(const int* __restrict__ ei, int* ws) {
    const int bid = blockIdx.x;                    // 0..NCSR-1
    const int gid = bid * 256 + threadIdx.x;
    const int stride = NCSR * 256;

    // phase 0: deg = 1 (self loops)
    for (int i = gid; i < NN; i += stride) g_deg[i] = 1;
    grid_bar(1);

    // phase 1: degree count
    for (int i = gid; i < EE; i += stride) atomicAdd(&g_deg[ei[EE + i]], 1);
    grid_bar(2);

    // phase 2a: per-block chunk sums
    const int CHUNK = (NN + NCSR - 1) / NCSR;      // 541
    const int lo = bid * CHUNK;
    const int hi = min(lo + CHUNK, NN);
    {
        int s = 0;
        for (int i = lo + threadIdx.x; i < hi; i += 256) s += g_deg[i];
        // block reduce
        #pragma unroll
        for (int o = 16; o; o >>= 1) s += __shfl_xor_sync(0xffffffffu, s, o);
        if ((threadIdx.x & 31) == 0) ws[threadIdx.x >> 5] = s;
        __syncthreads();
        if (threadIdx.x == 0) {
            int t2 = 0;
            #pragma unroll
            for (int j = 0; j < 8; j++) t2 += ws[j];
            g_bsum[bid] = t2;
        }
        __syncthreads();
    }
    grid_bar(3);

    // phase 2b: block 0 scans the NCSR chunk sums
    if (bid == 0) {
        int v = (threadIdx.x < NCSR) ? g_bsum[threadIdx.x] : 0;
        int inc = iscan256(v, ws);
        if (threadIdx.x < NCSR) g_bpre[threadIdx.x] = inc - v;
        __syncthreads();
    }
    grid_bar(4);

    // phase 2c: scan own chunk, write off + cur
    {
        int carry = g_bpre[bid];
        for (int base = lo; base < hi; base += 256) {
            int i = base + threadIdx.x;
            int v = (i < hi) ? g_deg[i] : 0;
            int inc = iscan256(v, ws);
            if (i < hi) {
                int o = carry + inc - v;
                g_off[i] = o;
                g_cur[i] = o;
            }
            carry += ws[8];
            __syncthreads();
        }
        if (bid == 0 && threadIdx.x == 0) g_off[NN] = ET;
    }
    grid_bar(5);

    // phase 3: scatter
    for (int i = gid; i < ET; i += stride) {
        int s, d;
        if (i < EE) { s = ei[i]; d = ei[EE + i]; }
        else        { s = i - EE; d = s; }
        int p = atomicAdd(&g_cur[d], 1);
        g_src[p] = s;
    }
}

// ---------------- fused: CSR build (blocks 0..147) || layer-0 GEMM (rest) ----------------
__global__ __launch_bounds__(256, 2) void fused_csr_gemm0(
    const int* __restrict__ ei,
    const float* __restrict__ A,
    const float* __restrict__ Wl, const float* __restrict__ bl,
    const float* __restrict__ Wr, const float* __restrict__ br)
{
    __shared__ GemmSmem sm;
    if (blockIdx.x < NCSR) {
        csr_block(ei, (int*)sm.Af);
    } else {
        gemm_block(sm, (blockIdx.x - NCSR) * 128, A, FIND, Wl, bl, Wr, br);
    }
}

// ---------------- standalone GEMM (layers 1,2) ----------------
__global__ __launch_bounds__(256, 2) void dual_linear_tc(
    const float* __restrict__ A, int fin,
    const float* __restrict__ Wl, const float* __restrict__ bl,
    const float* __restrict__ Wr, const float* __restrict__ br)
{
    __shared__ GemmSmem sm;
    gemm_block(sm, blockIdx.x * 128, A, fin, Wl, bl, Wr, br);
}

// ---------------- half-warp-per-node online-softmax edge pass (8-edge batch) ----------------
template <bool FINAL>
__global__ __launch_bounds__(256) void gat_edge_half(
    const float* __restrict__ att, const float* __restrict__ b,
    float* __restrict__ hout,
    const float* __restrict__ Wro, const float* __restrict__ bro,
    float* __restrict__ out)
{
    __shared__ float Ws[OUTD * HH];
    if (FINAL) {
        for (int i = threadIdx.x; i < OUTD * HH; i += blockDim.x) Ws[i] = Wro[i];
        __syncthreads();
    }

    int lane = threadIdx.x & 31;
    int half = lane >> 4;
    int sl   = lane & 15;
    unsigned hm = 0xFFFFu << (half * 16);

    int node = (blockIdx.x * (blockDim.x >> 5) + (threadIdx.x >> 5)) * 2 + half;
    if (node >= NN) return;

    const float4 att4 = *(const float4*)(att + 4 * sl);
    const float4 xr4  = *(const float4*)(g_xr + (size_t)node * HH + 4 * sl);

    int s = g_off[node], e = g_off[node + 1];

    float m = -3.0e38f, d = 0.f;
    float4 acc = make_float4(0.f, 0.f, 0.f, 0.f);

    for (int i = s; i < e; i += 8) {
        float4 a[8];
        float  p[8];
        #pragma unroll
        for (int j = 0; j < 8; j++) {
            int src = (i + j < e) ? __ldg(g_src + i + j) : node;
            a[j] = *(const float4*)(g_xl + (size_t)src * HH + 4 * sl);
        }
        #pragma unroll
        for (int j = 0; j < 8; j++) {
            float t0 = a[j].x + xr4.x; t0 = t0 > 0.f ? t0 : 0.2f * t0;
            float t1 = a[j].y + xr4.y; t1 = t1 > 0.f ? t1 : 0.2f * t1;
            float t2 = a[j].z + xr4.z; t2 = t2 > 0.f ? t2 : 0.2f * t2;
            float t3 = a[j].w + xr4.w; t3 = t3 > 0.f ? t3 : 0.2f * t3;
            float q = t0 * att4.x + t1 * att4.y + t2 * att4.z + t3 * att4.w;
            p[j] = (i + j < e) ? q : -3.0e38f;
        }
        // 8 independent width-16 butterfly chains
        #pragma unroll
        for (int o = 8; o; o >>= 1) {
            #pragma unroll
            for (int j = 0; j < 8; j++)
                p[j] += __shfl_xor_sync(hm, p[j], o, 16);
        }
        float m8 = p[0];
        #pragma unroll
        for (int j = 1; j < 8; j++) m8 = fmaxf(m8, p[j]);
        if (m8 > m) {                        // uniform within the half
            float sc = __expf(m - m8);
            d *= sc; acc.x *= sc; acc.y *= sc; acc.z *= sc; acc.w *= sc;
            m = m8;
        }
        #pragma unroll
        for (int j = 0; j < 8; j++) {
            float w = __expf(p[j] - m);      // padded -> 0
            d += w;
            acc.x += w * a[j].x; acc.y += w * a[j].y;
            acc.z += w * a[j].z; acc.w += w * a[j].w;
        }
    }

    float inv = __fdividef(1.f, d);
    const float4 b4 = *(const float4*)(b + 4 * sl);
    float4 o4;
    o4.x = fmaxf(acc.x * inv + b4.x, 0.f);
    o4.y = fmaxf(acc.y * inv + b4.y, 0.f);
    o4.z = fmaxf(acc.z * inv + b4.z, 0.f);
    o4.w = fmaxf(acc.w * inv + b4.w, 0.f);

    if (!FINAL) {
        *(float4*)(hout + (size_t)node * HH + 4 * sl) = o4;
    } else {
        #pragma unroll
        for (int o = 0; o < OUTD; o++) {
            const float4 w4 = *(const float4*)(Ws + o * HH + 4 * sl);
            float q = o4.x * w4.x + o4.y * w4.y + o4.z * w4.z + o4.w * w4.w;
            #pragma unroll
            for (int r = 8; r; r >>= 1) q += __shfl_xor_sync(hm, q, r, 16);
            if (sl == 0) out[(size_t)node * OUTD + o] = q + __ldg(bro + o);
        }
    }
}

// ---------------- launch ----------------
extern "C" void kernel_launch(void* const* d_in, const int* in_sizes, int n_in,
                              void* d_out, int out_size)
{
    const float* x  = (const float*)d_in[0];
    const int*   ei = (const int*)d_in[1];
    const float* Wl0 = (const float*)d_in[3];
    const float* bl0 = (const float*)d_in[4];
    const float* Wr0 = (const float*)d_in[5];
    const float* br0 = (const float*)d_in[6];
    const float* at0 = (const float*)d_in[7];
    const float* b0  = (const float*)d_in[8];
    const float* Wl1 = (const float*)d_in[9];
    const float* bl1 = (const float*)d_in[10];
    const float* Wr1 = (const float*)d_in[11];
    const float* br1 = (const float*)d_in[12];
    const float* at1 = (const float*)d_in[13];
    const float* b1  = (const float*)d_in[14];
    const float* Wl2 = (const float*)d_in[15];
    const float* bl2 = (const float*)d_in[16];
    const float* Wr2 = (const float*)d_in[17];
    const float* br2 = (const float*)d_in[18];
    const float* at2 = (const float*)d_in[19];
    const float* b2  = (const float*)d_in[20];
    const float* Wro = (const float*)d_in[21];
    const float* bro = (const float*)d_in[22];
    float* out = (float*)d_out;

    float *h1p, *h2p;
    void  *barp;
    cudaGetSymbolAddress((void**)&h1p, g_h1);
    cudaGetSymbolAddress((void**)&h2p, g_h2);
    cudaGetSymbolAddress(&barp, g_bar);

    const int GB = NN / 128;             // 625 GEMM blocks
    const int EB = NN / 16;              // 5000 edge blocks (16 nodes each)

    cudaMemsetAsync(barp, 0, sizeof(unsigned));
    fused_csr_gemm0<<<NCSR + GB, 256>>>(ei, x, Wl0, bl0, Wr0, br0);
    gat_edge_half<false><<<EB, 256>>>(at0, b0, h1p, nullptr, nullptr, nullptr);
    dual_linear_tc<<<GB, 256>>>(h1p, HH, Wl1, bl1, Wr1, br1);
    gat_edge_half<false><<<EB, 256>>>(at1, b1, h2p, nullptr, nullptr, nullptr);
    dual_linear_tc<<<GB, 256>>>(h2p, HH, Wl2, bl2, Wr2, br2);
    gat_edge_half<true><<<EB, 256>>>(at2, b2, nullptr, Wro, bro, out);
}